// round 15
// baseline (speedup 1.0000x reference)
#include <cuda_runtime.h>
#include <mma.h>
#include <cuda_fp16.h>
#include <math.h>
#include <cstdint>

using namespace nvcuda;

#define S_  1024
#define B_  8
#define D_  1024
#define H_  16
#define HD_ 64
#define F_  4096
#define E_  8
#define NTOK (S_ * B_)      // 8192 tokens
#define D3_ (3 * D_)        // 3072

// ---------------- scratch (device globals: no allocs allowed) ----------------
__device__ __half g_qkvh [(size_t)NTOK * D3_];
__device__ __half g_projh[(size_t)NTOK * D_];
__device__ __half g_moeh[(size_t)NTOK * D_];
__device__ __half g_srch [(size_t)NTOK * D_];
__device__ __half g_inwh [(size_t)D3_ * D_];
__device__ __half g_outwh[(size_t)D_ * D_];
__device__ __half g_w1h  [(size_t)E_ * F_ * D_];
__device__ __half g_w2h  [(size_t)E_ * D_ * F_];
__device__ __half g_attnh[(size_t)NTOK * D_];
__device__ __half g_x1h  [(size_t)NTOK * D_];
__device__ __half g_hh   [(size_t)NTOK * F_];

// ---------------------------------------------------------------------------
// PTX helpers
// ---------------------------------------------------------------------------
__device__ __forceinline__ void cp_async16(unsigned int smem_addr,
                                           const void* gptr, bool valid)
{
    int sz = valid ? 16 : 0;
    asm volatile("cp.async.cg.shared.global [%0], [%1], 16, %2;\n"
                 :: "r"(smem_addr), "l"(gptr), "r"(sz));
}
__device__ __forceinline__ void cp_commit() {
    asm volatile("cp.async.commit_group;\n");
}
__device__ __forceinline__ void cp_wait2() {
    asm volatile("cp.async.wait_group 2;\n");
}

// fp16 mma m16n8k16, fp32 accumulate in place
__device__ __forceinline__ void mma_h16(float d[4], const unsigned a[4],
                                        const unsigned b[2])
{
    asm volatile(
        "mma.sync.aligned.m16n8k16.row.col.f32.f16.f16.f32 "
        "{%0,%1,%2,%3}, {%4,%5,%6,%7}, {%8,%9}, {%0,%1,%2,%3};"
        : "+f"(d[0]), "+f"(d[1]), "+f"(d[2]), "+f"(d[3])
        : "r"(a[0]), "r"(a[1]), "r"(a[2]), "r"(a[3]), "r"(b[0]), "r"(b[1]));
}

// ---------------------------------------------------------------------------
// Fused fp32 -> fp16 convert of ALL five tensors, one launch.
// ---------------------------------------------------------------------------
#define U_SRC  1048576
#define U_INW  (U_SRC + 393216)
#define U_OUTW (U_INW + 131072)
#define U_W1   (U_OUTW + 4194304)
#define U_W2   (U_W1 + 4194304)

__global__ void __launch_bounds__(256)
f2h_all(const float* __restrict__ src, const float* __restrict__ inw,
        const float* __restrict__ outw, const float* __restrict__ w1,
        const float* __restrict__ w2,
        __half* __restrict__ srch, __half* __restrict__ inwh,
        __half* __restrict__ outwh, __half* __restrict__ w1h,
        __half* __restrict__ w2h)
{
    int u = blockIdx.x * 256 + threadIdx.x;
    const float* in;
    __half* out;
    int off;
    if (u < U_SRC)       { in = src;  out = srch;  off = u; }
    else if (u < U_INW)  { in = inw;  out = inwh;  off = u - U_SRC; }
    else if (u < U_OUTW) { in = outw; out = outwh; off = u - U_INW; }
    else if (u < U_W1)   { in = w1;   out = w1h;   off = u - U_OUTW; }
    else                 { in = w2;   out = w2h;   off = u - U_W1; }
    size_t i = (size_t)off * 8;
    float4 a = *(const float4*)(in + i);
    float4 b = *(const float4*)(in + i + 4);
    __half2 h0 = __floats2half2_rn(a.x, a.y);
    __half2 h1 = __floats2half2_rn(a.z, a.w);
    __half2 h2 = __floats2half2_rn(b.x, b.y);
    __half2 h3 = __floats2half2_rn(b.z, b.w);
    uint4 v;
    v.x = *(unsigned*)&h0; v.y = *(unsigned*)&h1;
    v.z = *(unsigned*)&h2; v.w = *(unsigned*)&h3;
    *(uint4*)(out + i) = v;
}

// ---------------------------------------------------------------------------
// fp16 WMMA GEMM (m16n16k16), 4-stage cp.async pipeline (issue 3 ahead),
// fp32 accumulate.  C[M,N] = A[M,K] @ W[N,K]^T + bias[N]  (+ReLU / half out)
// Block tile 128x128, BK=32, 256 threads = 8 warps, warp tile 32x64.
// Dynamic smem: 4 stages x (A,B) 128x40 halfs = 81920 bytes.
// ---------------------------------------------------------------------------
#define HBK  32
#define HAST 40   // half stride (32 + 8 pad); 80 bytes/row
#define GST_BYTES (128 * HAST * 2)          // one stage of one matrix: 10240 B
#define GSMEM (8 * GST_BYTES)               // 81920 B

template<bool RELU, bool MOE, bool HOUT>
__global__ void __launch_bounds__(256, 2)
gemm_h(const __half* __restrict__ Abase, int lda,
       const __half* __restrict__ Wbase, int ldb,
       const float* __restrict__ biasbase,
       float* __restrict__ C32, __half* __restrict__ C16, int ldc,
       int M, int N, int K, size_t wstride, int bstride)
{
    extern __shared__ __align__(16) __half dsm[];
    __half* Ah = dsm;                      // 4 stages
    __half* Bh = dsm + 4 * 128 * HAST;     // 4 stages

    const int tid  = threadIdx.x;
    const int warp = tid >> 5;
    const int lane = tid & 31;
    const int wm   = warp & 3;
    const int wn   = warp >> 2;
    const int n0   = blockIdx.x * 128;

    int m0, Mb;
    const __half* A = Abase;
    const __half* W = Wbase;
    const float* bias = biasbase;
    if (MOE) {
        const int tcnt[8] = {54, 7, 2, 1, 1, 1, 1, 1};
        const int toff[8] = {0, 6852, 7709, 7963, 8070, 8125, 8157, 8177};
        const int tn[8]   = {6852, 857, 254, 107, 55, 32, 20, 15};
        int y = blockIdx.y, e = 0, acc = 0;
        while (y >= acc + tcnt[e]) { acc += tcnt[e]; e++; }
        m0 = toff[e] + (y - acc) * 128;
        Mb = toff[e] + tn[e];
        W    = Wbase + (size_t)e * wstride;
        bias = biasbase + (size_t)e * bstride;
    } else {
        m0 = blockIdx.y * 128;
        Mb = M;
    }

    const int lrow = tid >> 2;          // 0..63
    const int lch  = tid & 3;           // 16B chunk: 8 halfs

    unsigned sA = (unsigned)__cvta_generic_to_shared(Ah);
    unsigned sB = (unsigned)__cvta_generic_to_shared(Bh);

    auto issue = [&](int stage, int k0) {
#pragma unroll
        for (int t = 0; t < 2; t++) {
            int row = lrow + t * 64;
            cp_async16(sA + stage * GST_BYTES + (row * HAST + lch * 8) * 2,
                       A + (size_t)(m0 + row) * lda + k0 + lch * 8,
                       m0 + row < Mb);
            cp_async16(sB + stage * GST_BYTES + (row * HAST + lch * 8) * 2,
                       W + (size_t)(n0 + row) * ldb + k0 + lch * 8,
                       n0 + row < N);
        }
    };

    wmma::fragment<wmma::accumulator, 16, 16, 16, float> accf[2][4];
#pragma unroll
    for (int i = 0; i < 2; i++)
#pragma unroll
        for (int j = 0; j < 4; j++)
            wmma::fill_fragment(accf[i][j], 0.0f);

    const int ntiles = K / HBK;     // >= 32 always
    issue(0, 0);       cp_commit();
    issue(1, HBK);     cp_commit();
    issue(2, 2 * HBK); cp_commit();

    for (int kt = 0; kt < ntiles; kt++) {
        const int cur = kt & 3;
        cp_wait2();            // stage kt resident (kt+1, kt+2 may be in flight)
        __syncthreads();       // all warps done with stage (kt-1) = (kt+3)&3
        if (kt + 3 < ntiles) {
            issue((kt + 3) & 3, (kt + 3) * HBK);
            cp_commit();
        }

        __half* Ac = Ah + cur * 128 * HAST;
        __half* Bc = Bh + cur * 128 * HAST;
#pragma unroll
        for (int kk = 0; kk < HBK; kk += 16) {
            wmma::fragment<wmma::matrix_a, 16, 16, 16, __half,
                           wmma::row_major> af[2];
            wmma::fragment<wmma::matrix_b, 16, 16, 16, __half,
                           wmma::col_major> bf[4];
#pragma unroll
            for (int i = 0; i < 2; i++)
                wmma::load_matrix_sync(af[i],
                    Ac + (wm * 32 + i * 16) * HAST + kk, HAST);
#pragma unroll
            for (int j = 0; j < 4; j++)
                wmma::load_matrix_sync(bf[j],
                    Bc + (wn * 64 + j * 16) * HAST + kk, HAST);
#pragma unroll
            for (int i = 0; i < 2; i++)
#pragma unroll
                for (int j = 0; j < 4; j++)
                    wmma::mma_sync(accf[i][j], af[i], bf[j], accf[i][j]);
        }
    }

    // epilogue
    __syncthreads();
    float* sb = (float*)dsm + warp * 256;
    const int er = lane >> 1;            // row 0..15
    const int ec = (lane & 1) * 8;       // col base 0 or 8
#pragma unroll
    for (int i = 0; i < 2; i++) {
#pragma unroll
        for (int j = 0; j < 4; j++) {
            wmma::store_matrix_sync(sb, accf[i][j], 16, wmma::mem_row_major);
            __syncwarp();
            int r = m0 + wm * 32 + i * 16 + er;
            int c = n0 + wn * 64 + j * 16 + ec;
            if (r < Mb) {
                float v[8];
#pragma unroll
                for (int q = 0; q < 8; q++) {
                    v[q] = sb[er * 16 + ec + q] + bias[c + q];
                    if (RELU) v[q] = fmaxf(v[q], 0.f);
                }
                if (HOUT) {
                    __half2 h0 = __floats2half2_rn(v[0], v[1]);
                    __half2 h1 = __floats2half2_rn(v[2], v[3]);
                    __half2 h2 = __floats2half2_rn(v[4], v[5]);
                    __half2 h3 = __floats2half2_rn(v[6], v[7]);
                    uint4 u;
                    u.x = *(unsigned*)&h0; u.y = *(unsigned*)&h1;
                    u.z = *(unsigned*)&h2; u.w = *(unsigned*)&h3;
                    *(uint4*)(C16 + (size_t)r * ldc + c) = u;
                } else {
                    *(float4*)(C32 + (size_t)r * ldc + c) =
                        make_float4(v[0], v[1], v[2], v[3]);
                    *(float4*)(C32 + (size_t)r * ldc + c + 4) =
                        make_float4(v[4], v[5], v[6], v[7]);
                }
            }
            __syncwarp();
        }
    }
}

// ---------------------------------------------------------------------------
// Flash attention, register-resident FA2, fp16 mma.m16n8k16 (R12: prefetch).
// ---------------------------------------------------------------------------
#define KST 72   // half stride for K/Vt/P rows

__global__ void __launch_bounds__(256)
attn_h(const __half* __restrict__ qkv, __half* __restrict__ out)
{
    __shared__ __half Ks[64 * KST];          // [key][d]
    __shared__ __half Vt[64 * KST];          // [d][key]
    __shared__ __half Ps[8 * 16 * KST];      // per-warp [row][key]

    const int tid  = threadIdx.x;
    const int warp = tid >> 5, lane = tid & 31;
    const int ra = lane >> 2, q4 = lane & 3;
    const int s0 = blockIdx.x * 128;
    const int b  = blockIdx.y >> 4, h = blockIdx.y & 15;
    __half* Pw = Ps + warp * 16 * KST;

    const int key0 = tid >> 3;
    const int key1 = (tid + 256) >> 3;
    const int d8   = (tid & 7) * 8;

    unsigned qa[4][4];
    {
        const __half2 sc = __half2half2(__float2half(0.125f));
        const int r0 = s0 + warp * 16;
        const __half* rowA = qkv + ((size_t)(r0 + ra) * B_ + b) * D3_ + h * HD_;
        const __half* rowB = qkv + ((size_t)(r0 + ra + 8) * B_ + b) * D3_ + h * HD_;
#pragma unroll
        for (int kk = 0; kk < 4; kk++) {
            __half2 v;
            v = __hmul2(*(const __half2*)(rowA + 16 * kk + 2 * q4), sc);
            qa[kk][0] = *(unsigned*)&v;
            v = __hmul2(*(const __half2*)(rowB + 16 * kk + 2 * q4), sc);
            qa[kk][1] = *(unsigned*)&v;
            v = __hmul2(*(const __half2*)(rowA + 16 * kk + 2 * q4 + 8), sc);
            qa[kk][2] = *(unsigned*)&v;
            v = __hmul2(*(const __half2*)(rowB + 16 * kk + 2 * q4 + 8), sc);
            qa[kk][3] = *(unsigned*)&v;
        }
    }

    float oa[8][4];
#pragma unroll
    for (int j = 0; j < 8; j++)
#pragma unroll
        for (int e = 0; e < 4; e++) oa[j][e] = 0.f;
    float m_a = -1e30f, m_b = -1e30f, l_a = 0.f, l_b = 0.f;

    uint4 kreg[2], vreg[2];
    auto prefetch = [&](int t0) {
        size_t base0 = ((size_t)(t0 + key0) * B_ + b) * D3_ + h * HD_ + d8;
        size_t base1 = ((size_t)(t0 + key1) * B_ + b) * D3_ + h * HD_ + d8;
        kreg[0] = *(const uint4*)(qkv + base0 + D_);
        vreg[0] = *(const uint4*)(qkv + base0 + 2 * D_);
        kreg[1] = *(const uint4*)(qkv + base1 + D_);
        vreg[1] = *(const uint4*)(qkv + base1 + 2 * D_);
    };
    prefetch(0);

    for (int t0 = 0; t0 < S_; t0 += 64) {
        {
            *(uint4*)(Ks + key0 * KST + d8) = kreg[0];
            *(uint4*)(Ks + key1 * KST + d8) = kreg[1];
            const __half* v0 = (const __half*)&vreg[0];
            const __half* v1 = (const __half*)&vreg[1];
#pragma unroll
            for (int q = 0; q < 8; q++) {
                Vt[(d8 + q) * KST + key0] = v0[q];
                Vt[(d8 + q) * KST + key1] = v1[q];
            }
        }
        __syncthreads();

        if (t0 + 64 < S_) prefetch(t0 + 64);

        float sacc[8][4];
#pragma unroll
        for (int j = 0; j < 8; j++)
#pragma unroll
            for (int e = 0; e < 4; e++) sacc[j][e] = 0.f;
#pragma unroll
        for (int kk = 0; kk < 4; kk++) {
#pragma unroll
            for (int j = 0; j < 8; j++) {
                unsigned bb[2];
                const __half* kr = Ks + (8 * j + ra) * KST + 16 * kk + 2 * q4;
                bb[0] = *(const unsigned*)(kr);
                bb[1] = *(const unsigned*)(kr + 8);
                mma_h16(sacc[j], qa[kk], bb);
            }
        }

        float mxa = sacc[0][0], mxb = sacc[0][2];
#pragma unroll
        for (int j = 0; j < 8; j++) {
            mxa = fmaxf(mxa, fmaxf(sacc[j][0], sacc[j][1]));
            mxb = fmaxf(mxb, fmaxf(sacc[j][2], sacc[j][3]));
        }
        mxa = fmaxf(mxa, __shfl_xor_sync(0xffffffffu, mxa, 1));
        mxa = fmaxf(mxa, __shfl_xor_sync(0xffffffffu, mxa, 2));
        mxb = fmaxf(mxb, __shfl_xor_sync(0xffffffffu, mxb, 1));
        mxb = fmaxf(mxb, __shfl_xor_sync(0xffffffffu, mxb, 2));

        float mna = fmaxf(m_a, mxa), mnb = fmaxf(m_b, mxb);
        float ca = __expf(m_a - mna), cb = __expf(m_b - mnb);
        m_a = mna; m_b = mnb;

        float sa = 0.f, sb2 = 0.f;
#pragma unroll
        for (int j = 0; j < 8; j++) {
            __half2 pA = __floats2half2_rn(__expf(sacc[j][0] - mna),
                                           __expf(sacc[j][1] - mna));
            __half2 pB = __floats2half2_rn(__expf(sacc[j][2] - mnb),
                                           __expf(sacc[j][3] - mnb));
            float2 fA = __half22float2(pA);
            float2 fB = __half22float2(pB);
            sa  += fA.x + fA.y;
            sb2 += fB.x + fB.y;
            *(__half2*)(Pw + ra * KST + 8 * j + 2 * q4)       = pA;
            *(__half2*)(Pw + (ra + 8) * KST + 8 * j + 2 * q4) = pB;
        }
        sa  += __shfl_xor_sync(0xffffffffu, sa, 1);
        sa  += __shfl_xor_sync(0xffffffffu, sa, 2);
        sb2 += __shfl_xor_sync(0xffffffffu, sb2, 1);
        sb2 += __shfl_xor_sync(0xffffffffu, sb2, 2);
        l_a = l_a * ca + sa;
        l_b = l_b * cb + sb2;

#pragma unroll
        for (int j = 0; j < 8; j++) {
            oa[j][0] *= ca; oa[j][1] *= ca;
            oa[j][2] *= cb; oa[j][3] *= cb;
        }
        __syncwarp();

#pragma unroll
        for (int kk = 0; kk < 4; kk++) {
            unsigned aa[4];
            aa[0] = *(const unsigned*)(Pw + ra * KST + 16 * kk + 2 * q4);
            aa[1] = *(const unsigned*)(Pw + (ra + 8) * KST + 16 * kk + 2 * q4);
            aa[2] = *(const unsigned*)(Pw + ra * KST + 16 * kk + 2 * q4 + 8);
            aa[3] = *(const unsigned*)(Pw + (ra + 8) * KST + 16 * kk + 2 * q4 + 8);
#pragma unroll
            for (int j = 0; j < 8; j++) {
                unsigned bb[2];
                const __half* vr = Vt + (8 * j + ra) * KST + 16 * kk + 2 * q4;
                bb[0] = *(const unsigned*)(vr);
                bb[1] = *(const unsigned*)(vr + 8);
                mma_h16(oa[j], aa, bb);
            }
        }
        __syncthreads();
    }

    {
        float inva = 1.f / l_a, invb = 1.f / l_b;
        const int r0 = s0 + warp * 16;
        __half* dstA = out + ((size_t)(r0 + ra) * B_ + b) * D_ + h * HD_;
        __half* dstB = out + ((size_t)(r0 + ra + 8) * B_ + b) * D_ + h * HD_;
#pragma unroll
        for (int j = 0; j < 8; j++) {
            *(__half2*)(dstA + 8 * j + 2 * q4) =
                __floats2half2_rn(oa[j][0] * inva, oa[j][1] * inva);
            *(__half2*)(dstB + 8 * j + 2 * q4) =
                __floats2half2_rn(oa[j][2] * invb, oa[j][3] * invb);
        }
    }
}

// ---------------------------------------------------------------------------
// out = LayerNorm(a + r) * gamma + beta
// A16: a is fp16 (else fp32).  O32: write fp32 out (else fp16 outh).
// ---------------------------------------------------------------------------
template<bool A16, bool O32>
__global__ void __launch_bounds__(256)
add_ln_kernel(const void* __restrict__ a_, const __half* __restrict__ r,
              const float* __restrict__ gamma, const float* __restrict__ beta,
              float* __restrict__ out, __half* __restrict__ outh)
{
    const int row = blockIdx.x;
    const int tid = threadIdx.x;
    __shared__ float ws[8], wq[8];
    __shared__ float red[2];

    const size_t base4 = (size_t)row * 256 + tid;
    float4 va;
    if (A16) {
        uint2 au = ((const uint2*)a_)[base4];
        float2 a0 = __half22float2(*(__half2*)&au.x);
        float2 a1 = __half22float2(*(__half2*)&au.y);
        va = make_float4(a0.x, a0.y, a1.x, a1.y);
    } else {
        va = ((const float4*)a_)[base4];
    }
    uint2  ru = ((const uint2*)r)[base4];
    float2 r0 = __half22float2(*(__half2*)&ru.x);
    float2 r1 = __half22float2(*(__half2*)&ru.y);
    float4 v = make_float4(va.x + r0.x, va.y + r0.y, va.z + r1.x, va.w + r1.y);

    float s  = v.x + v.y + v.z + v.w;
    float sq = v.x * v.x + v.y * v.y + v.z * v.z + v.w * v.w;
#pragma unroll
    for (int o = 16; o > 0; o >>= 1) {
        s  += __shfl_xor_sync(0xffffffffu, s, o);
        sq += __shfl_xor_sync(0xffffffffu, sq, o);
    }
    int lane = tid & 31, wid = tid >> 5;
    if (lane == 0) { ws[wid] = s; wq[wid] = sq; }
    __syncthreads();
    if (tid == 0) {
        float Ssum = 0.f, Q = 0.f;
#pragma unroll
        for (int w = 0; w < 8; w++) { Ssum += ws[w]; Q += wq[w]; }
        float mu  = Ssum * (1.0f / D_);
        float var = Q * (1.0f / D_) - mu * mu;
        red[0] = mu;
        red[1] = rsqrtf(var + 1e-5f);
    }
    __syncthreads();
    const float mu = red[0], rstd = red[1];

    float4 g  = ((const float4*)gamma)[tid];
    float4 be = ((const float4*)beta)[tid];
    float4 o;
    o.x = (v.x - mu) * rstd * g.x + be.x;
    o.y = (v.y - mu) * rstd * g.y + be.y;
    o.z = (v.z - mu) * rstd * g.z + be.z;
    o.w = (v.w - mu) * rstd * g.w + be.w;
    if (O32) {
        ((float4*)out)[base4] = o;
    } else {
        __half2 h0 = __floats2half2_rn(o.x, o.y);
        __half2 h1 = __floats2half2_rn(o.z, o.w);
        uint2 u;
        u.x = *(unsigned*)&h0;
        u.y = *(unsigned*)&h1;
        ((uint2*)outh)[base4] = u;
    }
}

// ---------------------------------------------------------------------------
extern "C" void kernel_launch(void* const* d_in, const int* in_sizes, int n_in,
                              void* d_out, int out_size)
{
    (void)in_sizes; (void)n_in; (void)out_size;
    const float* src  = (const float*)d_in[0];
    const float* inw  = (const float*)d_in[1];
    const float* inb  = (const float*)d_in[2];
    const float* outw = (const float*)d_in[3];
    const float* outb = (const float*)d_in[4];
    const float* g1   = (const float*)d_in[5];
    const float* be1  = (const float*)d_in[6];
    const float* g2   = (const float*)d_in[7];
    const float* be2  = (const float*)d_in[8];
    const float* w1   = (const float*)d_in[9];
    const float* b1   = (const float*)d_in[10];
    const float* w2   = (const float*)d_in[11];
    const float* b2   = (const float*)d_in[12];
    float* out = (float*)d_out;

    __half *qkvh, *projh, *moeh, *srch, *inwh, *outwh, *w1h, *w2h;
    __half *attnh, *x1h, *hh;
    cudaGetSymbolAddress((void**)&qkvh,  g_qkvh);
    cudaGetSymbolAddress((void**)&projh, g_projh);
    cudaGetSymbolAddress((void**)&moeh,  g_moeh);
    cudaGetSymbolAddress((void**)&srch,  g_srch);
    cudaGetSymbolAddress((void**)&inwh,  g_inwh);
    cudaGetSymbolAddress((void**)&outwh, g_outwh);
    cudaGetSymbolAddress((void**)&w1h,   g_w1h);
    cudaGetSymbolAddress((void**)&w2h,   g_w2h);
    cudaGetSymbolAddress((void**)&attnh, g_attnh);
    cudaGetSymbolAddress((void**)&x1h,   g_x1h);
    cudaGetSymbolAddress((void**)&hh,    g_hh);

    cudaFuncSetAttribute(gemm_h<false, false, true>,
                         cudaFuncAttributeMaxDynamicSharedMemorySize, GSMEM);
    cudaFuncSetAttribute(gemm_h<true, true, true>,
                         cudaFuncAttributeMaxDynamicSharedMemorySize, GSMEM);
    cudaFuncSetAttribute(gemm_h<false, true, true>,
                         cudaFuncAttributeMaxDynamicSharedMemorySize, GSMEM);

    dim3 blk(256);

    // 0) all fp16 conversions in ONE launch
    f2h_all<<<U_W2 / 256, blk>>>(src, inw, outw, w1, w2,
                                 srch, inwh, outwh, w1h, w2h);

    // 1) qkv = src @ in_proj_w^T + b   [8192 x 3072], fp16 out
    gemm_h<false, false, true><<<dim3(D3_ / 128, NTOK / 128), blk, GSMEM>>>(
        srch, D_, inwh, D_, inb, nullptr, qkvh, D3_, NTOK, D3_, D_, 0, 0);

    // 2) attention -> attnh [8192 x 1024] (fp16 in/out)
    attn_h<<<dim3(S_ / 128, B_ * H_), blk>>>(qkvh, attnh);

    // 3) proj = attn @ out_proj_w^T + b [8192 x 1024], fp16 out
    gemm_h<false, false, true><<<dim3(D_ / 128, NTOK / 128), blk, GSMEM>>>(
        attnh, D_, outwh, D_, outb, nullptr, projh, D_, NTOK, D_, D_, 0, 0);

    // 4) x1h = LN(src + proj)  (fp16 only; src fp32)
    add_ln_kernel<false, false><<<NTOK, blk>>>(src, projh, g1, be1,
                                               nullptr, x1h);

    // 5) MoE: batched expert GEMMs; h fp16; moe fp16
    gemm_h<true, true, true><<<dim3(F_ / 128, 68), blk, GSMEM>>>(
        x1h, D_, w1h, D_, b1, nullptr, hh, F_, NTOK, F_, D_,
        (size_t)F_ * D_, F_);
    gemm_h<false, true, true><<<dim3(D_ / 128, 68), blk, GSMEM>>>(
        hh, F_, w2h, F_, b2, nullptr, moeh, D_, NTOK, D_, F_,
        (size_t)D_ * F_, D_);

    // 6) out = LN(x1h + moe)  (a fp16, fp32 out)
    add_ln_kernel<true, true><<<NTOK, blk>>>(x1h, moeh, g2, be2, out, nullptr);
}

// round 16
// speedup vs baseline: 1.0634x; 1.0634x over previous
#include <cuda_runtime.h>
#include <mma.h>
#include <cuda_fp16.h>
#include <math.h>
#include <cstdint>

using namespace nvcuda;

#define S_  1024
#define B_  8
#define D_  1024
#define H_  16
#define HD_ 64
#define F_  4096
#define E_  8
#define NTOK (S_ * B_)      // 8192 tokens
#define D3_ (3 * D_)        // 3072

// ---------------- scratch (device globals: no allocs allowed) ----------------
__device__ __half g_qkvh [(size_t)NTOK * D3_];
__device__ __half g_projh[(size_t)NTOK * D_];
__device__ __half g_moeh[(size_t)NTOK * D_];
__device__ __half g_srch [(size_t)NTOK * D_];
__device__ __half g_inwh [(size_t)D3_ * D_];
__device__ __half g_outwh[(size_t)D_ * D_];
__device__ __half g_w1h  [(size_t)E_ * F_ * D_];
__device__ __half g_w2h  [(size_t)E_ * D_ * F_];
__device__ __half g_attnh[(size_t)NTOK * D_];
__device__ __half g_x1h  [(size_t)NTOK * D_];
__device__ __half g_hh   [(size_t)NTOK * F_];

// ---------------------------------------------------------------------------
// PTX helpers
// ---------------------------------------------------------------------------
__device__ __forceinline__ void cp_async16(unsigned int smem_addr,
                                           const void* gptr, bool valid)
{
    int sz = valid ? 16 : 0;
    asm volatile("cp.async.cg.shared.global [%0], [%1], 16, %2;\n"
                 :: "r"(smem_addr), "l"(gptr), "r"(sz));
}
__device__ __forceinline__ void cp_commit() {
    asm volatile("cp.async.commit_group;\n");
}
__device__ __forceinline__ void cp_wait1() {
    asm volatile("cp.async.wait_group 1;\n");
}

// fp16 mma m16n8k16, fp32 accumulate in place
__device__ __forceinline__ void mma_h16(float d[4], const unsigned a[4],
                                        const unsigned b[2])
{
    asm volatile(
        "mma.sync.aligned.m16n8k16.row.col.f32.f16.f16.f32 "
        "{%0,%1,%2,%3}, {%4,%5,%6,%7}, {%8,%9}, {%0,%1,%2,%3};"
        : "+f"(d[0]), "+f"(d[1]), "+f"(d[2]), "+f"(d[3])
        : "r"(a[0]), "r"(a[1]), "r"(a[2]), "r"(a[3]), "r"(b[0]), "r"(b[1]));
}

// ---------------------------------------------------------------------------
// Fused fp32 -> fp16 convert of ALL five tensors, one launch.
// ---------------------------------------------------------------------------
#define U_SRC  1048576
#define U_INW  (U_SRC + 393216)
#define U_OUTW (U_INW + 131072)
#define U_W1   (U_OUTW + 4194304)
#define U_W2   (U_W1 + 4194304)

__global__ void __launch_bounds__(256)
f2h_all(const float* __restrict__ src, const float* __restrict__ inw,
        const float* __restrict__ outw, const float* __restrict__ w1,
        const float* __restrict__ w2,
        __half* __restrict__ srch, __half* __restrict__ inwh,
        __half* __restrict__ outwh, __half* __restrict__ w1h,
        __half* __restrict__ w2h)
{
    int u = blockIdx.x * 256 + threadIdx.x;
    const float* in;
    __half* out;
    int off;
    if (u < U_SRC)       { in = src;  out = srch;  off = u; }
    else if (u < U_INW)  { in = inw;  out = inwh;  off = u - U_SRC; }
    else if (u < U_OUTW) { in = outw; out = outwh; off = u - U_INW; }
    else if (u < U_W1)   { in = w1;   out = w1h;   off = u - U_OUTW; }
    else                 { in = w2;   out = w2h;   off = u - U_W1; }
    size_t i = (size_t)off * 8;
    float4 a = *(const float4*)(in + i);
    float4 b = *(const float4*)(in + i + 4);
    __half2 h0 = __floats2half2_rn(a.x, a.y);
    __half2 h1 = __floats2half2_rn(a.z, a.w);
    __half2 h2 = __floats2half2_rn(b.x, b.y);
    __half2 h3 = __floats2half2_rn(b.z, b.w);
    uint4 v;
    v.x = *(unsigned*)&h0; v.y = *(unsigned*)&h1;
    v.z = *(unsigned*)&h2; v.w = *(unsigned*)&h3;
    *(uint4*)(out + i) = v;
}

// ---------------------------------------------------------------------------
// fp16 WMMA GEMM (m16n16k16), 3-stage cp.async pipeline, fp32 accumulate.
//   C[M,N] = A[M,K] @ W[N,K]^T + bias[N]   (optional ReLU, optional half out)
// Block tile 128x128, BK=64 (4 k16 steps per barrier), 8 warps, warp tile
// 32x64. Dynamic smem: 3 stages x (A,B) 128x72 halfs = 110592 bytes. (R14)
// ---------------------------------------------------------------------------
#define HBK  64
#define HAST 72   // half stride (64 + 8 pad); 144 bytes/row
#define GST_BYTES (128 * HAST * 2)          // one stage of one matrix: 18432 B
#define GSMEM (6 * GST_BYTES)               // 110592 B

template<bool RELU, bool MOE, bool HOUT>
__global__ void __launch_bounds__(256, 2)
gemm_h(const __half* __restrict__ Abase, int lda,
       const __half* __restrict__ Wbase, int ldb,
       const float* __restrict__ biasbase,
       float* __restrict__ C32, __half* __restrict__ C16, int ldc,
       int M, int N, int K, size_t wstride, int bstride)
{
    extern __shared__ __align__(16) __half dsm[];
    __half* Ah = dsm;                      // 3 stages
    __half* Bh = dsm + 3 * 128 * HAST;     // 3 stages

    const int tid  = threadIdx.x;
    const int warp = tid >> 5;
    const int lane = tid & 31;
    const int wm   = warp & 3;
    const int wn   = warp >> 2;
    const int n0   = blockIdx.x * 128;

    int m0, Mb;
    const __half* A = Abase;
    const __half* W = Wbase;
    const float* bias = biasbase;
    if (MOE) {
        const int tcnt[8] = {54, 7, 2, 1, 1, 1, 1, 1};
        const int toff[8] = {0, 6852, 7709, 7963, 8070, 8125, 8157, 8177};
        const int tn[8]   = {6852, 857, 254, 107, 55, 32, 20, 15};
        int y = blockIdx.y, e = 0, acc = 0;
        while (y >= acc + tcnt[e]) { acc += tcnt[e]; e++; }
        m0 = toff[e] + (y - acc) * 128;
        Mb = toff[e] + tn[e];
        W    = Wbase + (size_t)e * wstride;
        bias = biasbase + (size_t)e * bstride;
    } else {
        m0 = blockIdx.y * 128;
        Mb = M;
    }

    unsigned sA = (unsigned)__cvta_generic_to_shared(Ah);
    unsigned sB = (unsigned)__cvta_generic_to_shared(Bh);

    // per stage: 128 rows x 8 chunks (8 halfs each) per matrix = 1024 slots
    auto issue = [&](int stage, int k0) {
#pragma unroll
        for (int t = 0; t < 4; t++) {
            int id  = tid + t * 256;
            int row = id >> 3;
            int ch  = (id & 7) * 8;
            cp_async16(sA + stage * GST_BYTES + (row * HAST + ch) * 2,
                       A + (size_t)(m0 + row) * lda + k0 + ch,
                       m0 + row < Mb);
            cp_async16(sB + stage * GST_BYTES + (row * HAST + ch) * 2,
                       W + (size_t)(n0 + row) * ldb + k0 + ch,
                       n0 + row < N);
        }
    };

    wmma::fragment<wmma::accumulator, 16, 16, 16, float> accf[2][4];
#pragma unroll
    for (int i = 0; i < 2; i++)
#pragma unroll
        for (int j = 0; j < 4; j++)
            wmma::fill_fragment(accf[i][j], 0.0f);

    const int ntiles = K / HBK;     // >= 16 always
    issue(0, 0);
    cp_commit();
    issue(1, HBK);
    cp_commit();

    for (int kt = 0; kt < ntiles; kt++) {
        const int cur = kt % 3;
        cp_wait1();            // stage kt resident (kt+1 may be in flight)
        __syncthreads();       // all warps done with stage (kt-1) = (kt+2)%3
        if (kt + 2 < ntiles)
            issue((kt + 2) % 3, (kt + 2) * HBK);
        cp_commit();

        __half* Ac = Ah + cur * 128 * HAST;
        __half* Bc = Bh + cur * 128 * HAST;
#pragma unroll
        for (int kk = 0; kk < HBK; kk += 16) {
            wmma::fragment<wmma::matrix_a, 16, 16, 16, __half,
                           wmma::row_major> af[2];
            wmma::fragment<wmma::matrix_b, 16, 16, 16, __half,
                           wmma::col_major> bf[4];
#pragma unroll
            for (int i = 0; i < 2; i++)
                wmma::load_matrix_sync(af[i],
                    Ac + (wm * 32 + i * 16) * HAST + kk, HAST);
#pragma unroll
            for (int j = 0; j < 4; j++)
                wmma::load_matrix_sync(bf[j],
                    Bc + (wn * 64 + j * 16) * HAST + kk, HAST);
#pragma unroll
            for (int i = 0; i < 2; i++)
#pragma unroll
                for (int j = 0; j < 4; j++)
                    wmma::mma_sync(accf[i][j], af[i], bf[j], accf[i][j]);
        }
    }

    // epilogue
    __syncthreads();
    float* sb = (float*)dsm + warp * 256;
    const int er = lane >> 1;            // row 0..15
    const int ec = (lane & 1) * 8;       // col base 0 or 8
#pragma unroll
    for (int i = 0; i < 2; i++) {
#pragma unroll
        for (int j = 0; j < 4; j++) {
            wmma::store_matrix_sync(sb, accf[i][j], 16, wmma::mem_row_major);
            __syncwarp();
            int r = m0 + wm * 32 + i * 16 + er;
            int c = n0 + wn * 64 + j * 16 + ec;
            if (r < Mb) {
                float v[8];
#pragma unroll
                for (int q = 0; q < 8; q++) {
                    v[q] = sb[er * 16 + ec + q] + bias[c + q];
                    if (RELU) v[q] = fmaxf(v[q], 0.f);
                }
                if (HOUT) {
                    __half2 h0 = __floats2half2_rn(v[0], v[1]);
                    __half2 h1 = __floats2half2_rn(v[2], v[3]);
                    __half2 h2 = __floats2half2_rn(v[4], v[5]);
                    __half2 h3 = __floats2half2_rn(v[6], v[7]);
                    uint4 u;
                    u.x = *(unsigned*)&h0; u.y = *(unsigned*)&h1;
                    u.z = *(unsigned*)&h2; u.w = *(unsigned*)&h3;
                    *(uint4*)(C16 + (size_t)r * ldc + c) = u;
                } else {
                    *(float4*)(C32 + (size_t)r * ldc + c) =
                        make_float4(v[0], v[1], v[2], v[3]);
                    *(float4*)(C32 + (size_t)r * ldc + c + 4) =
                        make_float4(v[4], v[5], v[6], v[7]);
                }
            }
            __syncwarp();
        }
    }
}

// ---------------------------------------------------------------------------
// Flash attention, register-resident FA2, fp16 mma.m16n8k16 (R12: prefetch).
// ---------------------------------------------------------------------------
#define KST 72   // half stride for K/Vt/P rows

__global__ void __launch_bounds__(256)
attn_h(const __half* __restrict__ qkv, __half* __restrict__ out)
{
    __shared__ __half Ks[64 * KST];          // [key][d]
    __shared__ __half Vt[64 * KST];          // [d][key]
    __shared__ __half Ps[8 * 16 * KST];      // per-warp [row][key]

    const int tid  = threadIdx.x;
    const int warp = tid >> 5, lane = tid & 31;
    const int ra = lane >> 2, q4 = lane & 3;
    const int s0 = blockIdx.x * 128;
    const int b  = blockIdx.y >> 4, h = blockIdx.y & 15;
    __half* Pw = Ps + warp * 16 * KST;

    const int key0 = tid >> 3;
    const int key1 = (tid + 256) >> 3;
    const int d8   = (tid & 7) * 8;

    unsigned qa[4][4];
    {
        const __half2 sc = __half2half2(__float2half(0.125f));
        const int r0 = s0 + warp * 16;
        const __half* rowA = qkv + ((size_t)(r0 + ra) * B_ + b) * D3_ + h * HD_;
        const __half* rowB = qkv + ((size_t)(r0 + ra + 8) * B_ + b) * D3_ + h * HD_;
#pragma unroll
        for (int kk = 0; kk < 4; kk++) {
            __half2 v;
            v = __hmul2(*(const __half2*)(rowA + 16 * kk + 2 * q4), sc);
            qa[kk][0] = *(unsigned*)&v;
            v = __hmul2(*(const __half2*)(rowB + 16 * kk + 2 * q4), sc);
            qa[kk][1] = *(unsigned*)&v;
            v = __hmul2(*(const __half2*)(rowA + 16 * kk + 2 * q4 + 8), sc);
            qa[kk][2] = *(unsigned*)&v;
            v = __hmul2(*(const __half2*)(rowB + 16 * kk + 2 * q4 + 8), sc);
            qa[kk][3] = *(unsigned*)&v;
        }
    }

    float oa[8][4];
#pragma unroll
    for (int j = 0; j < 8; j++)
#pragma unroll
        for (int e = 0; e < 4; e++) oa[j][e] = 0.f;
    float m_a = -1e30f, m_b = -1e30f, l_a = 0.f, l_b = 0.f;

    uint4 kreg[2], vreg[2];
    auto prefetch = [&](int t0) {
        size_t base0 = ((size_t)(t0 + key0) * B_ + b) * D3_ + h * HD_ + d8;
        size_t base1 = ((size_t)(t0 + key1) * B_ + b) * D3_ + h * HD_ + d8;
        kreg[0] = *(const uint4*)(qkv + base0 + D_);
        vreg[0] = *(const uint4*)(qkv + base0 + 2 * D_);
        kreg[1] = *(const uint4*)(qkv + base1 + D_);
        vreg[1] = *(const uint4*)(qkv + base1 + 2 * D_);
    };
    prefetch(0);

    for (int t0 = 0; t0 < S_; t0 += 64) {
        {
            *(uint4*)(Ks + key0 * KST + d8) = kreg[0];
            *(uint4*)(Ks + key1 * KST + d8) = kreg[1];
            const __half* v0 = (const __half*)&vreg[0];
            const __half* v1 = (const __half*)&vreg[1];
#pragma unroll
            for (int q = 0; q < 8; q++) {
                Vt[(d8 + q) * KST + key0] = v0[q];
                Vt[(d8 + q) * KST + key1] = v1[q];
            }
        }
        __syncthreads();

        if (t0 + 64 < S_) prefetch(t0 + 64);

        float sacc[8][4];
#pragma unroll
        for (int j = 0; j < 8; j++)
#pragma unroll
            for (int e = 0; e < 4; e++) sacc[j][e] = 0.f;
#pragma unroll
        for (int kk = 0; kk < 4; kk++) {
#pragma unroll
            for (int j = 0; j < 8; j++) {
                unsigned bb[2];
                const __half* kr = Ks + (8 * j + ra) * KST + 16 * kk + 2 * q4;
                bb[0] = *(const unsigned*)(kr);
                bb[1] = *(const unsigned*)(kr + 8);
                mma_h16(sacc[j], qa[kk], bb);
            }
        }

        float mxa = sacc[0][0], mxb = sacc[0][2];
#pragma unroll
        for (int j = 0; j < 8; j++) {
            mxa = fmaxf(mxa, fmaxf(sacc[j][0], sacc[j][1]));
            mxb = fmaxf(mxb, fmaxf(sacc[j][2], sacc[j][3]));
        }
        mxa = fmaxf(mxa, __shfl_xor_sync(0xffffffffu, mxa, 1));
        mxa = fmaxf(mxa, __shfl_xor_sync(0xffffffffu, mxa, 2));
        mxb = fmaxf(mxb, __shfl_xor_sync(0xffffffffu, mxb, 1));
        mxb = fmaxf(mxb, __shfl_xor_sync(0xffffffffu, mxb, 2));

        float mna = fmaxf(m_a, mxa), mnb = fmaxf(m_b, mxb);
        float ca = __expf(m_a - mna), cb = __expf(m_b - mnb);
        m_a = mna; m_b = mnb;

        float sa = 0.f, sb2 = 0.f;
#pragma unroll
        for (int j = 0; j < 8; j++) {
            __half2 pA = __floats2half2_rn(__expf(sacc[j][0] - mna),
                                           __expf(sacc[j][1] - mna));
            __half2 pB = __floats2half2_rn(__expf(sacc[j][2] - mnb),
                                           __expf(sacc[j][3] - mnb));
            float2 fA = __half22float2(pA);
            float2 fB = __half22float2(pB);
            sa  += fA.x + fA.y;
            sb2 += fB.x + fB.y;
            *(__half2*)(Pw + ra * KST + 8 * j + 2 * q4)       = pA;
            *(__half2*)(Pw + (ra + 8) * KST + 8 * j + 2 * q4) = pB;
        }
        sa  += __shfl_xor_sync(0xffffffffu, sa, 1);
        sa  += __shfl_xor_sync(0xffffffffu, sa, 2);
        sb2 += __shfl_xor_sync(0xffffffffu, sb2, 1);
        sb2 += __shfl_xor_sync(0xffffffffu, sb2, 2);
        l_a = l_a * ca + sa;
        l_b = l_b * cb + sb2;

#pragma unroll
        for (int j = 0; j < 8; j++) {
            oa[j][0] *= ca; oa[j][1] *= ca;
            oa[j][2] *= cb; oa[j][3] *= cb;
        }
        __syncwarp();

#pragma unroll
        for (int kk = 0; kk < 4; kk++) {
            unsigned aa[4];
            aa[0] = *(const unsigned*)(Pw + ra * KST + 16 * kk + 2 * q4);
            aa[1] = *(const unsigned*)(Pw + (ra + 8) * KST + 16 * kk + 2 * q4);
            aa[2] = *(const unsigned*)(Pw + ra * KST + 16 * kk + 2 * q4 + 8);
            aa[3] = *(const unsigned*)(Pw + (ra + 8) * KST + 16 * kk + 2 * q4 + 8);
#pragma unroll
            for (int j = 0; j < 8; j++) {
                unsigned bb[2];
                const __half* vr = Vt + (8 * j + ra) * KST + 16 * kk + 2 * q4;
                bb[0] = *(const unsigned*)(vr);
                bb[1] = *(const unsigned*)(vr + 8);
                mma_h16(oa[j], aa, bb);
            }
        }
        __syncthreads();
    }

    {
        float inva = 1.f / l_a, invb = 1.f / l_b;
        const int r0 = s0 + warp * 16;
        __half* dstA = out + ((size_t)(r0 + ra) * B_ + b) * D_ + h * HD_;
        __half* dstB = out + ((size_t)(r0 + ra + 8) * B_ + b) * D_ + h * HD_;
#pragma unroll
        for (int j = 0; j < 8; j++) {
            *(__half2*)(dstA + 8 * j + 2 * q4) =
                __floats2half2_rn(oa[j][0] * inva, oa[j][1] * inva);
            *(__half2*)(dstB + 8 * j + 2 * q4) =
                __floats2half2_rn(oa[j][2] * invb, oa[j][3] * invb);
        }
    }
}

// ---------------------------------------------------------------------------
// out = LayerNorm(a + r) * gamma + beta
// A16: a is fp16 (else fp32).  O32: write fp32 out (else fp16 outh).
// ---------------------------------------------------------------------------
template<bool A16, bool O32>
__global__ void __launch_bounds__(256)
add_ln_kernel(const void* __restrict__ a_, const __half* __restrict__ r,
              const float* __restrict__ gamma, const float* __restrict__ beta,
              float* __restrict__ out, __half* __restrict__ outh)
{
    const int row = blockIdx.x;
    const int tid = threadIdx.x;
    __shared__ float ws[8], wq[8];
    __shared__ float red[2];

    const size_t base4 = (size_t)row * 256 + tid;
    float4 va;
    if (A16) {
        uint2 au = ((const uint2*)a_)[base4];
        float2 a0 = __half22float2(*(__half2*)&au.x);
        float2 a1 = __half22float2(*(__half2*)&au.y);
        va = make_float4(a0.x, a0.y, a1.x, a1.y);
    } else {
        va = ((const float4*)a_)[base4];
    }
    uint2  ru = ((const uint2*)r)[base4];
    float2 r0 = __half22float2(*(__half2*)&ru.x);
    float2 r1 = __half22float2(*(__half2*)&ru.y);
    float4 v = make_float4(va.x + r0.x, va.y + r0.y, va.z + r1.x, va.w + r1.y);

    float s  = v.x + v.y + v.z + v.w;
    float sq = v.x * v.x + v.y * v.y + v.z * v.z + v.w * v.w;
#pragma unroll
    for (int o = 16; o > 0; o >>= 1) {
        s  += __shfl_xor_sync(0xffffffffu, s, o);
        sq += __shfl_xor_sync(0xffffffffu, sq, o);
    }
    int lane = tid & 31, wid = tid >> 5;
    if (lane == 0) { ws[wid] = s; wq[wid] = sq; }
    __syncthreads();
    if (tid == 0) {
        float Ssum = 0.f, Q = 0.f;
#pragma unroll
        for (int w = 0; w < 8; w++) { Ssum += ws[w]; Q += wq[w]; }
        float mu  = Ssum * (1.0f / D_);
        float var = Q * (1.0f / D_) - mu * mu;
        red[0] = mu;
        red[1] = rsqrtf(var + 1e-5f);
    }
    __syncthreads();
    const float mu = red[0], rstd = red[1];

    float4 g  = ((const float4*)gamma)[tid];
    float4 be = ((const float4*)beta)[tid];
    float4 o;
    o.x = (v.x - mu) * rstd * g.x + be.x;
    o.y = (v.y - mu) * rstd * g.y + be.y;
    o.z = (v.z - mu) * rstd * g.z + be.z;
    o.w = (v.w - mu) * rstd * g.w + be.w;
    if (O32) {
        ((float4*)out)[base4] = o;
    } else {
        __half2 h0 = __floats2half2_rn(o.x, o.y);
        __half2 h1 = __floats2half2_rn(o.z, o.w);
        uint2 u;
        u.x = *(unsigned*)&h0;
        u.y = *(unsigned*)&h1;
        ((uint2*)outh)[base4] = u;
    }
}

// ---------------------------------------------------------------------------
extern "C" void kernel_launch(void* const* d_in, const int* in_sizes, int n_in,
                              void* d_out, int out_size)
{
    (void)in_sizes; (void)n_in; (void)out_size;
    const float* src  = (const float*)d_in[0];
    const float* inw  = (const float*)d_in[1];
    const float* inb  = (const float*)d_in[2];
    const float* outw = (const float*)d_in[3];
    const float* outb = (const float*)d_in[4];
    const float* g1   = (const float*)d_in[5];
    const float* be1  = (const float*)d_in[6];
    const float* g2   = (const float*)d_in[7];
    const float* be2  = (const float*)d_in[8];
    const float* w1   = (const float*)d_in[9];
    const float* b1   = (const float*)d_in[10];
    const float* w2   = (const float*)d_in[11];
    const float* b2   = (const float*)d_in[12];
    float* out = (float*)d_out;

    __half *qkvh, *projh, *moeh, *srch, *inwh, *outwh, *w1h, *w2h;
    __half *attnh, *x1h, *hh;
    cudaGetSymbolAddress((void**)&qkvh,  g_qkvh);
    cudaGetSymbolAddress((void**)&projh, g_projh);
    cudaGetSymbolAddress((void**)&moeh,  g_moeh);
    cudaGetSymbolAddress((void**)&srch,  g_srch);
    cudaGetSymbolAddress((void**)&inwh,  g_inwh);
    cudaGetSymbolAddress((void**)&outwh, g_outwh);
    cudaGetSymbolAddress((void**)&w1h,   g_w1h);
    cudaGetSymbolAddress((void**)&w2h,   g_w2h);
    cudaGetSymbolAddress((void**)&attnh, g_attnh);
    cudaGetSymbolAddress((void**)&x1h,   g_x1h);
    cudaGetSymbolAddress((void**)&hh,    g_hh);

    cudaFuncSetAttribute(gemm_h<false, false, true>,
                         cudaFuncAttributeMaxDynamicSharedMemorySize, GSMEM);
    cudaFuncSetAttribute(gemm_h<true, true, true>,
                         cudaFuncAttributeMaxDynamicSharedMemorySize, GSMEM);
    cudaFuncSetAttribute(gemm_h<false, true, true>,
                         cudaFuncAttributeMaxDynamicSharedMemorySize, GSMEM);

    dim3 blk(256);

    // 0) all fp16 conversions in ONE launch
    f2h_all<<<U_W2 / 256, blk>>>(src, inw, outw, w1, w2,
                                 srch, inwh, outwh, w1h, w2h);

    // 1) qkv = src @ in_proj_w^T + b   [8192 x 3072], fp16 out
    gemm_h<false, false, true><<<dim3(D3_ / 128, NTOK / 128), blk, GSMEM>>>(
        srch, D_, inwh, D_, inb, nullptr, qkvh, D3_, NTOK, D3_, D_, 0, 0);

    // 2) attention -> attnh [8192 x 1024] (fp16 in/out)
    attn_h<<<dim3(S_ / 128, B_ * H_), blk>>>(qkvh, attnh);

    // 3) proj = attn @ out_proj_w^T + b [8192 x 1024], fp16 out
    gemm_h<false, false, true><<<dim3(D_ / 128, NTOK / 128), blk, GSMEM>>>(
        attnh, D_, outwh, D_, outb, nullptr, projh, D_, NTOK, D_, D_, 0, 0);

    // 4) x1h = LN(src + proj)  (fp16 only; src fp32)
    add_ln_kernel<false, false><<<NTOK, blk>>>(src, projh, g1, be1,
                                               nullptr, x1h);

    // 5) MoE: batched expert GEMMs; h fp16; moe fp16
    gemm_h<true, true, true><<<dim3(F_ / 128, 68), blk, GSMEM>>>(
        x1h, D_, w1h, D_, b1, nullptr, hh, F_, NTOK, F_, D_,
        (size_t)F_ * D_, F_);
    gemm_h<false, true, true><<<dim3(D_ / 128, 68), blk, GSMEM>>>(
        hh, F_, w2h, F_, b2, nullptr, moeh, D_, NTOK, D_, F_,
        (size_t)D_ * F_, D_);

    // 6) out = LN(x1h + moe)  (a fp16, fp32 out)
    add_ln_kernel<true, true><<<NTOK, blk>>>(x1h, moeh, g2, be2, out, nullptr);
}